// round 6
// baseline (speedup 1.0000x reference)
#include <cuda_runtime.h>

#define NBINS 256
#define NWARPS 8          // warps per block in histogram kernel (256 threads)

// ---------------- device-global scratch (no allocations allowed) -------------
__device__ unsigned int g_hist255[NBINS]; // histogram assuming normalized (scale=255)
__device__ unsigned int g_hist1[NBINS];   // histogram with scale=1 (fallback path)
__device__ int          g_flag;      // 1 if any element > 1.0f  (=> NOT normalized)
__device__ float        g_alpha;     // alpha_eff
__device__ float        g_beta;      // beta_eff
__device__ float        g_hi;        // clamp hi
__device__ int          g_adjust;    // 1 => apply affine+clamp, 0 => passthrough

// ---------------- k0: re-init globals (graphs replay => must reset) ----------
__global__ void k0_init() {
    int t = threadIdx.x;
    if (t < NBINS) { g_hist255[t] = 0u; g_hist1[t] = 0u; }
    if (t == 0)    g_flag = 0;
}

// ---------------- shared helper: one pixel into per-warp shared histogram ----
__device__ __forceinline__ void hist_one(float x0, float x1, float x2, float scale,
                                         unsigned int* h) {
    // match reference exactly: img_h = image*scale;
    // gray = (0.299*h0 + 0.587*h1) + 0.114*h2   (left-assoc, NO fma contraction)
    float h0 = __fmul_rn(x0, scale);
    float h1 = __fmul_rn(x1, scale);
    float h2 = __fmul_rn(x2, scale);
    float g  = __fadd_rn(__fadd_rn(__fmul_rn(0.299f, h0), __fmul_rn(0.587f, h1)),
                         __fmul_rn(0.114f, h2));
    if (g >= 0.0f && g <= 255.0f) {
        const float binw = 255.0f / 256.0f;   // 0.99609375, exact in f32
        int idx = (int)floorf(__fdiv_rn(g, binw));
        idx = idx < 0 ? 0 : (idx > 255 ? 255 : idx);
        atomicAdd(&h[idx], 1u);
    }
}

// ---------------- kA: FUSED flag + histogram@scale=255 (expected path) -------
// Software-pipelined: prefetch next iteration's 3 float4s before consuming the
// current ones, so 6 LDG.128 are in flight across the ATOMS chain (MLP_eff~6).
__global__ void kA_flag_hist(const float* __restrict__ img, int npix) {
    __shared__ unsigned int sh[NWARPS][NBINS];
    int tid  = threadIdx.x;
    int warp = tid >> 5;
    for (int i = tid; i < NWARPS * NBINS; i += blockDim.x)
        ((unsigned int*)sh)[i] = 0u;
    __syncthreads();

    const float4* c0 = (const float4*)img;
    const float4* c1 = (const float4*)(img + npix);
    const float4* c2 = (const float4*)(img + 2 * npix);
    int n4 = npix >> 2;
    unsigned int* myh = sh[warp];

    bool f = false;
    int stride = gridDim.x * blockDim.x;
    int i = blockIdx.x * blockDim.x + tid;

    if (i < n4) {
        float4 a = c0[i], b = c1[i], c = c2[i];
        for (int j = i + stride; j < n4; j += stride) {
            float4 an = c0[j], bn = c1[j], cn = c2[j];   // prefetch next
            f |= (a.x > 1.0f) | (a.y > 1.0f) | (a.z > 1.0f) | (a.w > 1.0f);
            f |= (b.x > 1.0f) | (b.y > 1.0f) | (b.z > 1.0f) | (b.w > 1.0f);
            f |= (c.x > 1.0f) | (c.y > 1.0f) | (c.z > 1.0f) | (c.w > 1.0f);
            hist_one(a.x, b.x, c.x, 255.0f, myh);
            hist_one(a.y, b.y, c.y, 255.0f, myh);
            hist_one(a.z, b.z, c.z, 255.0f, myh);
            hist_one(a.w, b.w, c.w, 255.0f, myh);
            a = an; b = bn; c = cn;
        }
        // epilogue: last resident tile
        f |= (a.x > 1.0f) | (a.y > 1.0f) | (a.z > 1.0f) | (a.w > 1.0f);
        f |= (b.x > 1.0f) | (b.y > 1.0f) | (b.z > 1.0f) | (b.w > 1.0f);
        f |= (c.x > 1.0f) | (c.y > 1.0f) | (c.z > 1.0f) | (c.w > 1.0f);
        hist_one(a.x, b.x, c.x, 255.0f, myh);
        hist_one(a.y, b.y, c.y, 255.0f, myh);
        hist_one(a.z, b.z, c.z, 255.0f, myh);
        hist_one(a.w, b.w, c.w, 255.0f, myh);
    }

    // scalar tail (npix not multiple of 4) — one thread
    if (blockIdx.x == 0 && tid == 0) {
        for (int k = n4 * 4; k < npix; k++) {
            float a = img[k], b = img[npix + k], c = img[2 * npix + k];
            f |= (a > 1.0f) | (b > 1.0f) | (c > 1.0f);
            hist_one(a, b, c, 255.0f, myh);
        }
    }
    if (__any_sync(0xffffffffu, f) && (tid & 31) == 0) g_flag = 1;
    __syncthreads();

    for (int k = tid; k < NBINS; k += blockDim.x) {
        unsigned int s = 0;
        #pragma unroll
        for (int w = 0; w < NWARPS; w++) s += sh[w][k];
        if (s) atomicAdd(&g_hist255[k], s);
    }
}

// ---------------- kB: conditional re-histogram @scale=1 (fallback path) ------
__global__ void kB_hist1(const float* __restrict__ img, int npix) {
    if (g_flag == 0) return;   // expected path: early-exit, ~no work

    __shared__ unsigned int sh[NWARPS][NBINS];
    int tid  = threadIdx.x;
    int warp = tid >> 5;
    for (int i = tid; i < NWARPS * NBINS; i += blockDim.x)
        ((unsigned int*)sh)[i] = 0u;
    __syncthreads();

    const float4* c0 = (const float4*)img;
    const float4* c1 = (const float4*)(img + npix);
    const float4* c2 = (const float4*)(img + 2 * npix);
    int n4 = npix >> 2;
    unsigned int* myh = sh[warp];

    int stride = gridDim.x * blockDim.x;
    for (int i = blockIdx.x * blockDim.x + tid; i < n4; i += stride) {
        float4 a = c0[i], b = c1[i], c = c2[i];
        hist_one(a.x, b.x, c.x, 1.0f, myh);
        hist_one(a.y, b.y, c.y, 1.0f, myh);
        hist_one(a.z, b.z, c.z, 1.0f, myh);
        hist_one(a.w, b.w, c.w, 1.0f, myh);
    }
    if (blockIdx.x == 0 && tid == 0) {
        for (int i = n4 * 4; i < npix; i++)
            hist_one(img[i], img[npix + i], img[2 * npix + i], 1.0f, myh);
    }
    __syncthreads();

    for (int i = tid; i < NBINS; i += blockDim.x) {
        unsigned int s = 0;
        #pragma unroll
        for (int w = 0; w < NWARPS; w++) s += sh[w][i];
        if (s) atomicAdd(&g_hist1[i], s);
    }
}

// ---------------- k3: finalize (cumsum / thresholds / params) ----------------
__global__ void k3_final() {
    if (threadIdx.x != 0 || blockIdx.x != 0) return;

    int   flag  = g_flag;
    float scale = flag ? 1.0f : 255.0f;
    const unsigned int* hist = flag ? g_hist1 : g_hist255;

    unsigned int total = 0;
    #pragma unroll 8
    for (int i = 0; i < NBINS; i++) total += hist[i];

    float maxv  = (float)total;                               // exact (<= 2^24)
    float cv    = __fmul_rn(__fdiv_rn(maxv, 100.0f), 0.5f);   // CLIP_HIST_PERCENT=1.0
    float upper = __fsub_rn(maxv, cv);

    unsigned int run = 0;
    int cnt_lo = 0, cnt_hi = 0;
    for (int i = 0; i < NBINS; i++) {
        run += hist[i];
        float a = (float)run;           // integer-valued f32 cumsum: exact, order-free
        cnt_lo += (a < cv)    ? 1 : 0;
        cnt_hi += (a < upper) ? 1 : 0;
    }
    int min_gray = cnt_lo;
    int max_gray = cnt_hi - 1;

    if (max_gray > min_gray) {
        int span    = max_gray - min_gray;                    // >= 1 here
        float alpha = __fdiv_rn(255.0f, (float)span);
        float beta  = __fmul_rn(-(float)min_gray, alpha);
        g_alpha  = __fdiv_rn(alpha, scale);
        g_beta   = __fdiv_rn(beta, scale);
        g_hi     = flag ? 255.0f : 1.0f;
        g_adjust = 1;
    } else {
        g_adjust = 0;
    }
}

// ---------------- k4: apply affine + clamp (or passthrough) ------------------
__global__ void k4_apply(const float4* __restrict__ in, float4* __restrict__ out, int n4,
                         const float* __restrict__ tin, float* __restrict__ tout, int ntail) {
    float a  = g_alpha;
    float b  = g_beta;
    float hi = g_hi;
    int adj  = g_adjust;

    int stride = gridDim.x * blockDim.x;
    if (adj) {
        for (int i = blockIdx.x * blockDim.x + threadIdx.x; i < n4; i += stride) {
            float4 v = in[i];
            v.x = fminf(fmaxf(v.x * a + b, 0.0f), hi);
            v.y = fminf(fmaxf(v.y * a + b, 0.0f), hi);
            v.z = fminf(fmaxf(v.z * a + b, 0.0f), hi);
            v.w = fminf(fmaxf(v.w * a + b, 0.0f), hi);
            out[i] = v;
        }
        if (blockIdx.x == 0 && threadIdx.x == 0) {
            for (int i = 0; i < ntail; i++)
                tout[i] = fminf(fmaxf(tin[i] * a + b, 0.0f), hi);
        }
    } else {
        for (int i = blockIdx.x * blockDim.x + threadIdx.x; i < n4; i += stride) {
            out[i] = in[i];
        }
        if (blockIdx.x == 0 && threadIdx.x == 0) {
            for (int i = 0; i < ntail; i++) tout[i] = tin[i];
        }
    }
}

// ---------------- launch ------------------------------------------------------
extern "C" void kernel_launch(void* const* d_in, const int* in_sizes, int n_in,
                              void* d_out, int out_size) {
    const float* img = (const float*)d_in[0];
    float* out = (float*)d_out;

    int ntot = in_sizes[0];        // 3 * H * W
    int npix = ntot / 3;           // per-channel pixel count
    int n4tot = ntot >> 2;
    int ntail = ntot - (n4tot << 2);

    const int T = 256;
    int sms = 148;                 // sm_100a SM count; grid-stride tolerates mismatch
    int g_stream = sms * 16;       // streaming apply kernel
    int g_hist_b = sms * 8;        // histogram kernels

    k0_init<<<1, 256>>>();
    kA_flag_hist<<<g_hist_b, T>>>(img, npix);
    kB_hist1<<<g_hist_b, T>>>(img, npix);
    k3_final<<<1, 32>>>();
    k4_apply<<<g_stream, T>>>((const float4*)img, (float4*)out, n4tot,
                              img + (size_t)(n4tot << 2),
                              out + (size_t)(n4tot << 2), ntail);
}

// round 8
// speedup vs baseline: 1.0178x; 1.0178x over previous
#include <cuda_runtime.h>

#define NBINS  256
#define NWARPS 8           // warps per block (256 threads)

// ---------------- device-global scratch (no allocations allowed) -------------
__device__ unsigned int g_hist255[NBINS]; // histogram assuming normalized (scale=255)
__device__ unsigned int g_hist1[NBINS];   // histogram with scale=1 (fallback path)
__device__ int          g_flag;           // 1 if any element > 1.0f (NOT normalized)
__device__ unsigned int g_bar0;           // grid barrier after speculative hist
__device__ unsigned int g_bar1;           // grid barrier after fallback hist

// ---------------- k0: re-init globals (graph replays reuse globals) ----------
__global__ void k0_init() {
    int t = threadIdx.x;
    if (t < NBINS) { g_hist255[t] = 0u; g_hist1[t] = 0u; }
    if (t == 0)    { g_flag = 0; g_bar0 = 0u; g_bar1 = 0u; }
}

// ---------------- helpers ----------------------------------------------------
__device__ __forceinline__ void hist_one(float x0, float x1, float x2, float scale,
                                         unsigned int* h) {
    // match reference exactly: img_h = image*scale;
    // gray = (0.299*h0 + 0.587*h1) + 0.114*h2   (left-assoc, NO fma contraction)
    float h0 = __fmul_rn(x0, scale);
    float h1 = __fmul_rn(x1, scale);
    float h2 = __fmul_rn(x2, scale);
    float g  = __fadd_rn(__fadd_rn(__fmul_rn(0.299f, h0), __fmul_rn(0.587f, h1)),
                         __fmul_rn(0.114f, h2));
    if (g >= 0.0f && g <= 255.0f) {
        const float binw = 255.0f / 256.0f;   // exact in f32
        int idx = (int)floorf(__fdiv_rn(g, binw));
        idx = idx < 0 ? 0 : (idx > 255 ? 255 : idx);
        atomicAdd(&h[idx], 1u);
    }
}

// grid barrier: monotonic counter, reset by k0_init each replay.
// Launch grid is sized from the occupancy API so ALL blocks are resident:
// the spin provably terminates.
__device__ __forceinline__ void grid_barrier(unsigned int* ctr) {
    __threadfence();               // release: this block's global writes visible
    __syncthreads();
    if (threadIdx.x == 0) {
        atomicAdd(ctr, 1u);
        while (*(volatile unsigned int*)ctr < (unsigned int)gridDim.x) __nanosleep(64);
    }
    __syncthreads();
    __threadfence();               // acquire: see all other blocks' writes
}

// ---------------- fused persistent kernel ------------------------------------
// Phase 1: flag + speculative histogram (scale=255)  -> barrier
// Phase 1b (only if flag): re-histogram (scale=1)    -> barrier
// Finalize: redundant per-block 256-bin scan (hist L2-resident, ~1us)
// Phase 2: apply affine+clamp (or passthrough)
__global__ void __launch_bounds__(256, 2)
fused_abc(const float* __restrict__ img, float* __restrict__ out,
          int npix, int ntot) {
    __shared__ unsigned int sh[NWARPS][NBINS];
    __shared__ unsigned int scan[NBINS];

    int tid  = threadIdx.x;
    int warp = tid >> 5;
    unsigned int* myh = sh[warp];

    for (int i = tid; i < NWARPS * NBINS; i += blockDim.x)
        ((unsigned int*)sh)[i] = 0u;
    __syncthreads();

    const float4* c0 = (const float4*)img;
    const float4* c1 = (const float4*)(img + npix);
    const float4* c2 = (const float4*)(img + 2 * npix);
    int n4     = npix >> 2;
    int stride = gridDim.x * blockDim.x;
    int base   = blockIdx.x * blockDim.x + tid;

    // ---- Phase 1: flag + hist@255, 2 tiles per iter (6 LDG.128 batched) ----
    bool f = false;
    {
        int i = base;
        for (; i + stride < n4; i += 2 * stride) {
            float4 a0 = c0[i],          b0 = c1[i],          d0 = c2[i];
            float4 a1 = c0[i + stride], b1 = c1[i + stride], d1 = c2[i + stride];
            f |= (a0.x > 1.0f) | (a0.y > 1.0f) | (a0.z > 1.0f) | (a0.w > 1.0f);
            f |= (b0.x > 1.0f) | (b0.y > 1.0f) | (b0.z > 1.0f) | (b0.w > 1.0f);
            f |= (d0.x > 1.0f) | (d0.y > 1.0f) | (d0.z > 1.0f) | (d0.w > 1.0f);
            f |= (a1.x > 1.0f) | (a1.y > 1.0f) | (a1.z > 1.0f) | (a1.w > 1.0f);
            f |= (b1.x > 1.0f) | (b1.y > 1.0f) | (b1.z > 1.0f) | (b1.w > 1.0f);
            f |= (d1.x > 1.0f) | (d1.y > 1.0f) | (d1.z > 1.0f) | (d1.w > 1.0f);
            hist_one(a0.x, b0.x, d0.x, 255.0f, myh);
            hist_one(a0.y, b0.y, d0.y, 255.0f, myh);
            hist_one(a0.z, b0.z, d0.z, 255.0f, myh);
            hist_one(a0.w, b0.w, d0.w, 255.0f, myh);
            hist_one(a1.x, b1.x, d1.x, 255.0f, myh);
            hist_one(a1.y, b1.y, d1.y, 255.0f, myh);
            hist_one(a1.z, b1.z, d1.z, 255.0f, myh);
            hist_one(a1.w, b1.w, d1.w, 255.0f, myh);
        }
        for (; i < n4; i += stride) {
            float4 a = c0[i], b = c1[i], d = c2[i];
            f |= (a.x > 1.0f) | (a.y > 1.0f) | (a.z > 1.0f) | (a.w > 1.0f);
            f |= (b.x > 1.0f) | (b.y > 1.0f) | (b.z > 1.0f) | (b.w > 1.0f);
            f |= (d.x > 1.0f) | (d.y > 1.0f) | (d.z > 1.0f) | (d.w > 1.0f);
            hist_one(a.x, b.x, d.x, 255.0f, myh);
            hist_one(a.y, b.y, d.y, 255.0f, myh);
            hist_one(a.z, b.z, d.z, 255.0f, myh);
            hist_one(a.w, b.w, d.w, 255.0f, myh);
        }
        // scalar tail (npix not multiple of 4) — one thread
        if (blockIdx.x == 0 && tid == 0) {
            for (int k = n4 * 4; k < npix; k++) {
                float a = img[k], b = img[npix + k], d = img[2 * npix + k];
                f |= (a > 1.0f) | (b > 1.0f) | (d > 1.0f);
                hist_one(a, b, d, 255.0f, myh);
            }
        }
    }
    if (__any_sync(0xffffffffu, f) && (tid & 31) == 0) g_flag = 1;
    __syncthreads();
    for (int k = tid; k < NBINS; k += blockDim.x) {
        unsigned int s = 0;
        #pragma unroll
        for (int w = 0; w < NWARPS; w++) s += sh[w][k];
        if (s) atomicAdd(&g_hist255[k], s);
    }

    grid_barrier(&g_bar0);

    int flag = g_flag;
    const unsigned int* hist = g_hist255;

    // ---- Phase 1b (fallback, flag==1 only): re-histogram with scale=1 ----
    if (flag) {
        for (int i = tid; i < NWARPS * NBINS; i += blockDim.x)
            ((unsigned int*)sh)[i] = 0u;
        __syncthreads();
        for (int i = base; i < n4; i += stride) {
            float4 a = c0[i], b = c1[i], d = c2[i];
            hist_one(a.x, b.x, d.x, 1.0f, myh);
            hist_one(a.y, b.y, d.y, 1.0f, myh);
            hist_one(a.z, b.z, d.z, 1.0f, myh);
            hist_one(a.w, b.w, d.w, 1.0f, myh);
        }
        if (blockIdx.x == 0 && tid == 0) {
            for (int k = n4 * 4; k < npix; k++)
                hist_one(img[k], img[npix + k], img[2 * npix + k], 1.0f, myh);
        }
        __syncthreads();
        for (int k = tid; k < NBINS; k += blockDim.x) {
            unsigned int s = 0;
            #pragma unroll
            for (int w = 0; w < NWARPS; w++) s += sh[w][k];
            if (s) atomicAdd(&g_hist1[k], s);
        }
        grid_barrier(&g_bar1);
        hist = g_hist1;
    }

    // ---- Finalize: redundant per-block integer scan (exact; hist in L2) ----
    scan[tid] = hist[tid];           // blockDim == NBINS == 256
    __syncthreads();
    #pragma unroll
    for (int off = 1; off < NBINS; off <<= 1) {
        unsigned int u = (tid >= off) ? scan[tid - off] : 0u;
        __syncthreads();
        scan[tid] += u;
        __syncthreads();
    }
    unsigned int total = scan[NBINS - 1];          // uniform across block
    float maxv  = (float)total;                                // exact (<= 2^24)
    float cv    = __fmul_rn(__fdiv_rn(maxv, 100.0f), 0.5f);    // CLIP=1.0
    float upper = __fsub_rn(maxv, cv);
    float acc   = (float)scan[tid];   // integer-valued f32: exact, matches jnp cumsum

    int cnt_lo = __syncthreads_count(acc < cv);
    int cnt_hi = __syncthreads_count(acc < upper);
    int min_gray = cnt_lo;
    int max_gray = cnt_hi - 1;

    float scale = flag ? 1.0f : 255.0f;
    float a_eff = 0.0f, b_eff = 0.0f, hi = 0.0f;
    int adjust = (max_gray > min_gray);
    if (adjust) {
        int span    = max_gray - min_gray;                     // >= 1 here
        float alpha = __fdiv_rn(255.0f, (float)span);
        float beta  = __fmul_rn(-(float)min_gray, alpha);
        a_eff = __fdiv_rn(alpha, scale);
        b_eff = __fdiv_rn(beta, scale);
        hi    = flag ? 255.0f : 1.0f;
    }

    // ---- Phase 2: apply (4 tiles per iter for MLP) ----
    const float4* in4  = (const float4*)img;
    float4*       out4 = (float4*)out;
    int n4t = ntot >> 2;
    if (adjust) {
        int i = base;
        for (; i + 3 * stride < n4t; i += 4 * stride) {
            float4 v0 = in4[i];
            float4 v1 = in4[i + stride];
            float4 v2 = in4[i + 2 * stride];
            float4 v3 = in4[i + 3 * stride];
            v0.x = fminf(fmaxf(v0.x * a_eff + b_eff, 0.0f), hi);
            v0.y = fminf(fmaxf(v0.y * a_eff + b_eff, 0.0f), hi);
            v0.z = fminf(fmaxf(v0.z * a_eff + b_eff, 0.0f), hi);
            v0.w = fminf(fmaxf(v0.w * a_eff + b_eff, 0.0f), hi);
            v1.x = fminf(fmaxf(v1.x * a_eff + b_eff, 0.0f), hi);
            v1.y = fminf(fmaxf(v1.y * a_eff + b_eff, 0.0f), hi);
            v1.z = fminf(fmaxf(v1.z * a_eff + b_eff, 0.0f), hi);
            v1.w = fminf(fmaxf(v1.w * a_eff + b_eff, 0.0f), hi);
            v2.x = fminf(fmaxf(v2.x * a_eff + b_eff, 0.0f), hi);
            v2.y = fminf(fmaxf(v2.y * a_eff + b_eff, 0.0f), hi);
            v2.z = fminf(fmaxf(v2.z * a_eff + b_eff, 0.0f), hi);
            v2.w = fminf(fmaxf(v2.w * a_eff + b_eff, 0.0f), hi);
            v3.x = fminf(fmaxf(v3.x * a_eff + b_eff, 0.0f), hi);
            v3.y = fminf(fmaxf(v3.y * a_eff + b_eff, 0.0f), hi);
            v3.z = fminf(fmaxf(v3.z * a_eff + b_eff, 0.0f), hi);
            v3.w = fminf(fmaxf(v3.w * a_eff + b_eff, 0.0f), hi);
            out4[i]              = v0;
            out4[i + stride]     = v1;
            out4[i + 2 * stride] = v2;
            out4[i + 3 * stride] = v3;
        }
        for (; i < n4t; i += stride) {
            float4 v = in4[i];
            v.x = fminf(fmaxf(v.x * a_eff + b_eff, 0.0f), hi);
            v.y = fminf(fmaxf(v.y * a_eff + b_eff, 0.0f), hi);
            v.z = fminf(fmaxf(v.z * a_eff + b_eff, 0.0f), hi);
            v.w = fminf(fmaxf(v.w * a_eff + b_eff, 0.0f), hi);
            out4[i] = v;
        }
        if (blockIdx.x == 0 && tid == 0) {
            for (int k = n4t * 4; k < ntot; k++)
                out[k] = fminf(fmaxf(img[k] * a_eff + b_eff, 0.0f), hi);
        }
    } else {
        int i = base;
        for (; i + 3 * stride < n4t; i += 4 * stride) {
            float4 v0 = in4[i];
            float4 v1 = in4[i + stride];
            float4 v2 = in4[i + 2 * stride];
            float4 v3 = in4[i + 3 * stride];
            out4[i]              = v0;
            out4[i + stride]     = v1;
            out4[i + 2 * stride] = v2;
            out4[i + 3 * stride] = v3;
        }
        for (; i < n4t; i += stride) out4[i] = in4[i];
        if (blockIdx.x == 0 && tid == 0) {
            for (int k = n4t * 4; k < ntot; k++) out[k] = img[k];
        }
    }
}

// ---------------- launch ------------------------------------------------------
extern "C" void kernel_launch(void* const* d_in, const int* in_sizes, int n_in,
                              void* d_out, int out_size) {
    const float* img = (const float*)d_in[0];
    float* out = (float*)d_out;

    int ntot = in_sizes[0];        // 3 * H * W
    int npix = ntot / 3;           // per-channel pixel count

    // Size the grid so every block is resident -> spin barrier cannot deadlock.
    // (Host attribute/occupancy queries: no allocation, legal during capture.)
    static int grid_b = 0;         // computed once; deterministic across calls
    if (grid_b == 0) {
        int dev = 0, sms = 0, bpm = 0;
        cudaGetDevice(&dev);
        cudaDeviceGetAttribute(&sms, cudaDevAttrMultiProcessorCount, dev);
        cudaOccupancyMaxActiveBlocksPerMultiprocessor(&bpm, fused_abc, 256, 0);
        if (sms <= 0) sms = 148;
        if (bpm <= 0) bpm = 1;
        if (bpm > 2) bpm = 2;      // matches __launch_bounds__ intent
        grid_b = sms * bpm;
    }

    k0_init<<<1, 256>>>();
    fused_abc<<<grid_b, 256>>>(img, out, npix, ntot);
}

// round 9
// speedup vs baseline: 1.0988x; 1.0796x over previous
#include <cuda_runtime.h>

#define NBINS  256
#define NWARPS 8           // warps per block (256 threads)
#define MAXBPM 4           // target resident blocks per SM

// ---------------- device-global scratch (no allocations allowed) -------------
__device__ unsigned int g_hist255[NBINS]; // histogram assuming normalized (scale=255)
__device__ unsigned int g_hist1[NBINS];   // histogram with scale=1 (fallback path)
__device__ int          g_flag;           // 1 if any element > 1.0f (NOT normalized)
__device__ unsigned int g_bar0;           // grid barrier after speculative hist
__device__ unsigned int g_bar1;           // grid barrier after fallback hist

// ---------------- k0: re-init globals (graph replays reuse globals) ----------
__global__ void k0_init() {
    int t = threadIdx.x;
    if (t < NBINS) { g_hist255[t] = 0u; g_hist1[t] = 0u; }
    if (t == 0)    { g_flag = 0; g_bar0 = 0u; g_bar1 = 0u; }
}

// ---------------- helpers ----------------------------------------------------
__device__ __forceinline__ void hist_one(float x0, float x1, float x2, float scale,
                                         unsigned int* h) {
    // match reference exactly: img_h = image*scale;
    // gray = (0.299*h0 + 0.587*h1) + 0.114*h2   (left-assoc, NO fma contraction)
    float h0 = __fmul_rn(x0, scale);
    float h1 = __fmul_rn(x1, scale);
    float h2 = __fmul_rn(x2, scale);
    float g  = __fadd_rn(__fadd_rn(__fmul_rn(0.299f, h0), __fmul_rn(0.587f, h1)),
                         __fmul_rn(0.114f, h2));
    if (g >= 0.0f && g <= 255.0f) {
        const float binw = 255.0f / 256.0f;   // exact in f32
        int idx = (int)floorf(__fdiv_rn(g, binw));
        idx = idx < 0 ? 0 : (idx > 255 ? 255 : idx);
        atomicAdd(&h[idx], 1u);
    }
}

// grid barrier: monotonic counter, reset by k0_init each replay.
// Launch grid is sized from the occupancy API so ALL blocks are resident:
// the spin provably terminates.
__device__ __forceinline__ void grid_barrier(unsigned int* ctr) {
    __threadfence();               // release: this block's global writes visible
    __syncthreads();
    if (threadIdx.x == 0) {
        atomicAdd(ctr, 1u);
        while (*(volatile unsigned int*)ctr < (unsigned int)gridDim.x) __nanosleep(64);
    }
    __syncthreads();
    __threadfence();               // acquire: see all other blocks' writes
}

// ---------------- fused persistent kernel ------------------------------------
// Phase 1: flag + speculative histogram (scale=255)  -> barrier
// Phase 1b (only if flag): re-histogram (scale=1)    -> barrier
// Finalize: redundant per-block 256-bin scan (hist L2-resident, ~1us)
// Phase 2: apply affine+clamp (or passthrough)
__global__ void __launch_bounds__(256, MAXBPM)
fused_abc(const float* __restrict__ img, float* __restrict__ out,
          int npix, int ntot) {
    __shared__ unsigned int sh[NWARPS][NBINS];
    __shared__ unsigned int scan[NBINS];

    int tid  = threadIdx.x;
    int warp = tid >> 5;
    unsigned int* myh = sh[warp];

    for (int i = tid; i < NWARPS * NBINS; i += blockDim.x)
        ((unsigned int*)sh)[i] = 0u;
    __syncthreads();

    const float4* c0 = (const float4*)img;
    const float4* c1 = (const float4*)(img + npix);
    const float4* c2 = (const float4*)(img + 2 * npix);
    int n4     = npix >> 2;
    int stride = gridDim.x * blockDim.x;
    int base   = blockIdx.x * blockDim.x + tid;

    // ---- Phase 1: flag + hist@255, 2 tiles per iter (6 LDG.128 batched) ----
    bool f = false;
    {
        int i = base;
        for (; i + stride < n4; i += 2 * stride) {
            float4 a0 = c0[i],          b0 = c1[i],          d0 = c2[i];
            float4 a1 = c0[i + stride], b1 = c1[i + stride], d1 = c2[i + stride];
            f |= (a0.x > 1.0f) | (a0.y > 1.0f) | (a0.z > 1.0f) | (a0.w > 1.0f);
            f |= (b0.x > 1.0f) | (b0.y > 1.0f) | (b0.z > 1.0f) | (b0.w > 1.0f);
            f |= (d0.x > 1.0f) | (d0.y > 1.0f) | (d0.z > 1.0f) | (d0.w > 1.0f);
            f |= (a1.x > 1.0f) | (a1.y > 1.0f) | (a1.z > 1.0f) | (a1.w > 1.0f);
            f |= (b1.x > 1.0f) | (b1.y > 1.0f) | (b1.z > 1.0f) | (b1.w > 1.0f);
            f |= (d1.x > 1.0f) | (d1.y > 1.0f) | (d1.z > 1.0f) | (d1.w > 1.0f);
            hist_one(a0.x, b0.x, d0.x, 255.0f, myh);
            hist_one(a0.y, b0.y, d0.y, 255.0f, myh);
            hist_one(a0.z, b0.z, d0.z, 255.0f, myh);
            hist_one(a0.w, b0.w, d0.w, 255.0f, myh);
            hist_one(a1.x, b1.x, d1.x, 255.0f, myh);
            hist_one(a1.y, b1.y, d1.y, 255.0f, myh);
            hist_one(a1.z, b1.z, d1.z, 255.0f, myh);
            hist_one(a1.w, b1.w, d1.w, 255.0f, myh);
        }
        for (; i < n4; i += stride) {
            float4 a = c0[i], b = c1[i], d = c2[i];
            f |= (a.x > 1.0f) | (a.y > 1.0f) | (a.z > 1.0f) | (a.w > 1.0f);
            f |= (b.x > 1.0f) | (b.y > 1.0f) | (b.z > 1.0f) | (b.w > 1.0f);
            f |= (d.x > 1.0f) | (d.y > 1.0f) | (d.z > 1.0f) | (d.w > 1.0f);
            hist_one(a.x, b.x, d.x, 255.0f, myh);
            hist_one(a.y, b.y, d.y, 255.0f, myh);
            hist_one(a.z, b.z, d.z, 255.0f, myh);
            hist_one(a.w, b.w, d.w, 255.0f, myh);
        }
        // scalar tail (npix not multiple of 4) — one thread
        if (blockIdx.x == 0 && tid == 0) {
            for (int k = n4 * 4; k < npix; k++) {
                float a = img[k], b = img[npix + k], d = img[2 * npix + k];
                f |= (a > 1.0f) | (b > 1.0f) | (d > 1.0f);
                hist_one(a, b, d, 255.0f, myh);
            }
        }
    }
    if (__any_sync(0xffffffffu, f) && (tid & 31) == 0) g_flag = 1;
    __syncthreads();
    for (int k = tid; k < NBINS; k += blockDim.x) {
        unsigned int s = 0;
        #pragma unroll
        for (int w = 0; w < NWARPS; w++) s += sh[w][k];
        if (s) atomicAdd(&g_hist255[k], s);
    }

    grid_barrier(&g_bar0);

    int flag = g_flag;
    const unsigned int* hist = g_hist255;

    // ---- Phase 1b (fallback, flag==1 only): re-histogram with scale=1 ----
    if (flag) {
        for (int i = tid; i < NWARPS * NBINS; i += blockDim.x)
            ((unsigned int*)sh)[i] = 0u;
        __syncthreads();
        for (int i = base; i < n4; i += stride) {
            float4 a = c0[i], b = c1[i], d = c2[i];
            hist_one(a.x, b.x, d.x, 1.0f, myh);
            hist_one(a.y, b.y, d.y, 1.0f, myh);
            hist_one(a.z, b.z, d.z, 1.0f, myh);
            hist_one(a.w, b.w, d.w, 1.0f, myh);
        }
        if (blockIdx.x == 0 && tid == 0) {
            for (int k = n4 * 4; k < npix; k++)
                hist_one(img[k], img[npix + k], img[2 * npix + k], 1.0f, myh);
        }
        __syncthreads();
        for (int k = tid; k < NBINS; k += blockDim.x) {
            unsigned int s = 0;
            #pragma unroll
            for (int w = 0; w < NWARPS; w++) s += sh[w][k];
            if (s) atomicAdd(&g_hist1[k], s);
        }
        grid_barrier(&g_bar1);
        hist = g_hist1;
    }

    // ---- Finalize: redundant per-block integer scan (exact; hist in L2) ----
    scan[tid] = hist[tid];           // blockDim == NBINS == 256
    __syncthreads();
    #pragma unroll
    for (int off = 1; off < NBINS; off <<= 1) {
        unsigned int u = (tid >= off) ? scan[tid - off] : 0u;
        __syncthreads();
        scan[tid] += u;
        __syncthreads();
    }
    unsigned int total = scan[NBINS - 1];          // uniform across block
    float maxv  = (float)total;                                // exact (<= 2^24)
    float cv    = __fmul_rn(__fdiv_rn(maxv, 100.0f), 0.5f);    // CLIP=1.0
    float upper = __fsub_rn(maxv, cv);
    float acc   = (float)scan[tid];   // integer-valued f32: exact, matches jnp cumsum

    int cnt_lo = __syncthreads_count(acc < cv);
    int cnt_hi = __syncthreads_count(acc < upper);
    int min_gray = cnt_lo;
    int max_gray = cnt_hi - 1;

    float scale = flag ? 1.0f : 255.0f;
    float a_eff = 0.0f, b_eff = 0.0f, hi = 0.0f;
    int adjust = (max_gray > min_gray);
    if (adjust) {
        int span    = max_gray - min_gray;                     // >= 1 here
        float alpha = __fdiv_rn(255.0f, (float)span);
        float beta  = __fmul_rn(-(float)min_gray, alpha);
        a_eff = __fdiv_rn(alpha, scale);
        b_eff = __fdiv_rn(beta, scale);
        hi    = flag ? 255.0f : 1.0f;
    }

    // ---- Phase 2: apply (4 tiles per iter for MLP) ----
    const float4* in4  = (const float4*)img;
    float4*       out4 = (float4*)out;
    int n4t = ntot >> 2;
    if (adjust) {
        int i = base;
        for (; i + 3 * stride < n4t; i += 4 * stride) {
            float4 v0 = in4[i];
            float4 v1 = in4[i + stride];
            float4 v2 = in4[i + 2 * stride];
            float4 v3 = in4[i + 3 * stride];
            v0.x = fminf(fmaxf(v0.x * a_eff + b_eff, 0.0f), hi);
            v0.y = fminf(fmaxf(v0.y * a_eff + b_eff, 0.0f), hi);
            v0.z = fminf(fmaxf(v0.z * a_eff + b_eff, 0.0f), hi);
            v0.w = fminf(fmaxf(v0.w * a_eff + b_eff, 0.0f), hi);
            v1.x = fminf(fmaxf(v1.x * a_eff + b_eff, 0.0f), hi);
            v1.y = fminf(fmaxf(v1.y * a_eff + b_eff, 0.0f), hi);
            v1.z = fminf(fmaxf(v1.z * a_eff + b_eff, 0.0f), hi);
            v1.w = fminf(fmaxf(v1.w * a_eff + b_eff, 0.0f), hi);
            v2.x = fminf(fmaxf(v2.x * a_eff + b_eff, 0.0f), hi);
            v2.y = fminf(fmaxf(v2.y * a_eff + b_eff, 0.0f), hi);
            v2.z = fminf(fmaxf(v2.z * a_eff + b_eff, 0.0f), hi);
            v2.w = fminf(fmaxf(v2.w * a_eff + b_eff, 0.0f), hi);
            v3.x = fminf(fmaxf(v3.x * a_eff + b_eff, 0.0f), hi);
            v3.y = fminf(fmaxf(v3.y * a_eff + b_eff, 0.0f), hi);
            v3.z = fminf(fmaxf(v3.z * a_eff + b_eff, 0.0f), hi);
            v3.w = fminf(fmaxf(v3.w * a_eff + b_eff, 0.0f), hi);
            out4[i]              = v0;
            out4[i + stride]     = v1;
            out4[i + 2 * stride] = v2;
            out4[i + 3 * stride] = v3;
        }
        for (; i < n4t; i += stride) {
            float4 v = in4[i];
            v.x = fminf(fmaxf(v.x * a_eff + b_eff, 0.0f), hi);
            v.y = fminf(fmaxf(v.y * a_eff + b_eff, 0.0f), hi);
            v.z = fminf(fmaxf(v.z * a_eff + b_eff, 0.0f), hi);
            v.w = fminf(fmaxf(v.w * a_eff + b_eff, 0.0f), hi);
            out4[i] = v;
        }
        if (blockIdx.x == 0 && tid == 0) {
            for (int k = n4t * 4; k < ntot; k++)
                out[k] = fminf(fmaxf(img[k] * a_eff + b_eff, 0.0f), hi);
        }
    } else {
        int i = base;
        for (; i + 3 * stride < n4t; i += 4 * stride) {
            float4 v0 = in4[i];
            float4 v1 = in4[i + stride];
            float4 v2 = in4[i + 2 * stride];
            float4 v3 = in4[i + 3 * stride];
            out4[i]              = v0;
            out4[i + stride]     = v1;
            out4[i + 2 * stride] = v2;
            out4[i + 3 * stride] = v3;
        }
        for (; i < n4t; i += stride) out4[i] = in4[i];
        if (blockIdx.x == 0 && tid == 0) {
            for (int k = n4t * 4; k < ntot; k++) out[k] = img[k];
        }
    }
}

// ---------------- launch ------------------------------------------------------
extern "C" void kernel_launch(void* const* d_in, const int* in_sizes, int n_in,
                              void* d_out, int out_size) {
    const float* img = (const float*)d_in[0];
    float* out = (float*)d_out;

    int ntot = in_sizes[0];        // 3 * H * W
    int npix = ntot / 3;           // per-channel pixel count

    // Size the grid so every block is resident -> spin barrier cannot deadlock.
    // (Host attribute/occupancy queries: no allocation, legal during capture.)
    static int grid_b = 0;         // computed once; deterministic across calls
    if (grid_b == 0) {
        int dev = 0, sms = 0, bpm = 0;
        cudaGetDevice(&dev);
        cudaDeviceGetAttribute(&sms, cudaDevAttrMultiProcessorCount, dev);
        cudaOccupancyMaxActiveBlocksPerMultiprocessor(&bpm, fused_abc, 256, 0);
        if (sms <= 0) sms = 148;
        if (bpm <= 0) bpm = 1;
        if (bpm > MAXBPM) bpm = MAXBPM;
        grid_b = sms * bpm;
    }

    k0_init<<<1, 256>>>();
    fused_abc<<<grid_b, 256>>>(img, out, npix, ntot);
}